// round 12
// baseline (speedup 1.0000x reference)
#include <cuda_runtime.h>
#include <cuda_bf16.h>
#include <cstdint>
#include <float.h>

// AttentionSelector (R12 = R11 + missing include fixed).
//  Identity: out[b] = sum_i w_i * L[i,:] where L = repre @ rel^T and
//  logit_i = L[i, labels[i]]. So:
//   K0 (convert): rel -> 2-way bf16 split (B1 + B2), transposed-padded [64][704].
//   K1 (gemm):    L[200000][64] = repre @ rel^T via mma.sync m16n8k16 bf16,
//                 2-way split on A too: D = A1B1 + A1B2 + A2B1 (err ~2^-16).
//   K2 (out):     per bag: max/softmax over gathered L[i][labels[i]],
//                 out[b][r] = sum_i e_i * L[i][r] / s + bias[r].
//  Cuts total L1 traffic ~3.3 GB -> ~0.7 GB (the measured ~16 TB/s L1
//  effective ceiling was the binding constraint in all prior rounds).
// scope/labels are int32 on device (JAX x64-disabled downgrades int64).

static constexpr int Dd   = 690;
static constexpr int Kpad = 704;
static constexpr int RR   = 53;
static constexpr int Npad = 64;
static constexpr int Mmax = 200000;
static constexpr int KC   = 32;          // k-chunk per smem stage
static constexpr int KI   = Kpad / KC;   // 22 k-iterations
static constexpr int SA   = 36;          // smem A row stride (bf16)
static constexpr int SB   = 36;          // smem B row stride (bf16)

__device__ float          g_L[(size_t)Mmax * Npad];       // 51.2 MB logits
__device__ __nv_bfloat16  g_B1[Npad * Kpad];              // rel split hi, [n][k]
__device__ __nv_bfloat16  g_B2[Npad * Kpad];              // rel split lo, [n][k]

__device__ __forceinline__ float wmax(float v) {
#pragma unroll
    for (int o = 16; o; o >>= 1) v = fmaxf(v, __shfl_xor_sync(0xffffffffu, v, o));
    return v;
}

#define MMA_BF16(c, a, b0_, b1_)                                              \
    asm volatile(                                                             \
        "mma.sync.aligned.m16n8k16.row.col.f32.bf16.bf16.f32 "                \
        "{%0,%1,%2,%3}, {%4,%5,%6,%7}, {%8,%9}, {%0,%1,%2,%3};"               \
        : "+f"((c)[0]), "+f"((c)[1]), "+f"((c)[2]), "+f"((c)[3])              \
        : "r"((a)[0]), "r"((a)[1]), "r"((a)[2]), "r"((a)[3]),                 \
          "r"(b0_), "r"(b1_))

// ---------------- K0: rel -> split-bf16, transposed + zero-padded ----------
__global__ void convert_kernel(const float* __restrict__ rel) {
    for (int idx = threadIdx.x; idx < Npad * Kpad; idx += blockDim.x) {
        const int n = idx / Kpad;
        const int k = idx - n * Kpad;
        float v = (n < RR && k < Dd) ? rel[n * Dd + k] : 0.f;
        const __nv_bfloat16 b1 = __float2bfloat16(v);
        const __nv_bfloat16 b2 = __float2bfloat16(v - __bfloat162float(b1));
        g_B1[idx] = b1;
        g_B2[idx] = b2;
    }
}

// ---------------- K1: L = repre @ rel^T (split-bf16 mma) -------------------
__global__ __launch_bounds__(256) void gemm_kernel(
    const float* __restrict__ repre, int Mrows)
{
    __shared__ __nv_bfloat16 sA1[128][SA];
    __shared__ __nv_bfloat16 sA2[128][SA];
    __shared__ __nv_bfloat16 sB1[Npad][SB];
    __shared__ __nv_bfloat16 sB2[Npad][SB];

    const int tid  = threadIdx.x;
    const int lane = tid & 31;
    const int wid  = tid >> 5;
    const int gid  = lane >> 2;   // 0..7
    const int tg   = lane & 3;    // 0..3
    const int wm   = wid & 3;     // 4 m-tiles of 32
    const int wn   = wid >> 2;    // 2 n-tiles of 32
    const int m0   = blockIdx.x * 128;

    float acc[2][4][4];
#pragma unroll
    for (int mi = 0; mi < 2; mi++)
#pragma unroll
        for (int ni = 0; ni < 4; ni++)
#pragma unroll
            for (int q = 0; q < 4; q++) acc[mi][ni][q] = 0.f;

    const uint32_t* gB1u = reinterpret_cast<const uint32_t*>(g_B1);
    const uint32_t* gB2u = reinterpret_cast<const uint32_t*>(g_B2);

    for (int kt = 0; kt < KI; kt++) {
        const int k0 = kt * KC;

        // stage A (128 x 32 f32 -> split bf16), 2048 float2 / 256 thr
#pragma unroll
        for (int it = 0; it < 8; it++) {
            const int idx = tid + it * 256;
            const int m = idx >> 4;
            const int p = idx & 15;              // float2 index (k pair)
            const int grow = m0 + m;
            const int gk = k0 + p * 2;
            float2 v = make_float2(0.f, 0.f);
            if (grow < Mrows && gk < Dd)
                v = *reinterpret_cast<const float2*>(repre + (size_t)grow * Dd + gk);
            __nv_bfloat162 h1, h2;
            h1.x = __float2bfloat16(v.x);
            h1.y = __float2bfloat16(v.y);
            h2.x = __float2bfloat16(v.x - __bfloat162float(h1.x));
            h2.y = __float2bfloat16(v.y - __bfloat162float(h1.y));
            *reinterpret_cast<__nv_bfloat162*>(&sA1[m][p * 2]) = h1;
            *reinterpret_cast<__nv_bfloat162*>(&sA2[m][p * 2]) = h2;
        }
        // stage B (64 x 32 bf16 x 2 splits), 1024 u32 per split
#pragma unroll
        for (int it = 0; it < 4; it++) {
            const int idx = tid + it * 256;
            const int n = idx >> 4;
            const int p = idx & 15;
            const uint32_t u1 = gB1u[n * (Kpad / 2) + (k0 >> 1) + p];
            const uint32_t u2 = gB2u[n * (Kpad / 2) + (k0 >> 1) + p];
            *reinterpret_cast<uint32_t*>(&sB1[n][p * 2]) = u1;
            *reinterpret_cast<uint32_t*>(&sB2[n][p * 2]) = u2;
        }
        __syncthreads();

#pragma unroll
        for (int s = 0; s < KC; s += 16) {
            uint32_t A1f[2][4], A2f[2][4];
#pragma unroll
            for (int mi = 0; mi < 2; mi++) {
                const int mb = wm * 32 + mi * 16;
                A1f[mi][0] = *reinterpret_cast<const uint32_t*>(&sA1[mb + gid    ][s + tg * 2]);
                A1f[mi][1] = *reinterpret_cast<const uint32_t*>(&sA1[mb + gid + 8][s + tg * 2]);
                A1f[mi][2] = *reinterpret_cast<const uint32_t*>(&sA1[mb + gid    ][s + tg * 2 + 8]);
                A1f[mi][3] = *reinterpret_cast<const uint32_t*>(&sA1[mb + gid + 8][s + tg * 2 + 8]);
                A2f[mi][0] = *reinterpret_cast<const uint32_t*>(&sA2[mb + gid    ][s + tg * 2]);
                A2f[mi][1] = *reinterpret_cast<const uint32_t*>(&sA2[mb + gid + 8][s + tg * 2]);
                A2f[mi][2] = *reinterpret_cast<const uint32_t*>(&sA2[mb + gid    ][s + tg * 2 + 8]);
                A2f[mi][3] = *reinterpret_cast<const uint32_t*>(&sA2[mb + gid + 8][s + tg * 2 + 8]);
            }
#pragma unroll
            for (int ni = 0; ni < 4; ni++) {
                const int nb = wn * 32 + ni * 8 + gid;
                const uint32_t b1a = *reinterpret_cast<const uint32_t*>(&sB1[nb][s + tg * 2]);
                const uint32_t b1b = *reinterpret_cast<const uint32_t*>(&sB1[nb][s + tg * 2 + 8]);
                const uint32_t b2a = *reinterpret_cast<const uint32_t*>(&sB2[nb][s + tg * 2]);
                const uint32_t b2b = *reinterpret_cast<const uint32_t*>(&sB2[nb][s + tg * 2 + 8]);
#pragma unroll
                for (int mi = 0; mi < 2; mi++) {
                    MMA_BF16(acc[mi][ni], A1f[mi], b1a, b1b);
                    MMA_BF16(acc[mi][ni], A1f[mi], b2a, b2b);
                    MMA_BF16(acc[mi][ni], A2f[mi], b1a, b1b);
                }
            }
        }
        __syncthreads();
    }

    // epilogue: store L fp32
#pragma unroll
    for (int mi = 0; mi < 2; mi++) {
#pragma unroll
        for (int ni = 0; ni < 4; ni++) {
            const int col = wn * 32 + ni * 8 + tg * 2;
            const int r0  = m0 + wm * 32 + mi * 16 + gid;
            if (r0 < Mrows)
                *reinterpret_cast<float2*>(&g_L[(size_t)r0 * Npad + col]) =
                    make_float2(acc[mi][ni][0], acc[mi][ni][1]);
            if (r0 + 8 < Mrows)
                *reinterpret_cast<float2*>(&g_L[(size_t)(r0 + 8) * Npad + col]) =
                    make_float2(acc[mi][ni][2], acc[mi][ni][3]);
        }
    }
}

// ---------------- K2: per-bag softmax-weighted sum of L rows ---------------
__global__ __launch_bounds__(256) void out_kernel(
    const float* __restrict__ bias,
    const int*   __restrict__ scope,
    const int*   __restrict__ labels,
    float* __restrict__ out,
    int num_bags)
{
    const int lane = threadIdx.x & 31;
    const int wid  = threadIdx.x >> 5;
    const int bag  = blockIdx.x * 8 + wid;
    if (bag >= num_bags) return;

    const int start = scope[2 * bag];
    const int end   = scope[2 * bag + 1];

    // pass 1: per-bag max of gathered logits (lane-parallel)
    float m = -FLT_MAX;
    for (int i = start + lane; i < end; i += 32)
        m = fmaxf(m, g_L[(size_t)i * Npad + labels[i]]);
    m = wmax(m);

    // pass 2: weighted accumulate of L rows (lane owns cols 2*lane, 2*lane+1)
    const int c0 = lane * 2;
    float2 acc = make_float2(0.f, 0.f);
    float s = 0.f;
    for (int i = start; i < end; i++) {
        const float l = g_L[(size_t)i * Npad + labels[i]];   // broadcast
        const float e = __expf(l - m);
        s += e;
        const float2 Lv = *reinterpret_cast<const float2*>(g_L + (size_t)i * Npad + c0);
        acc.x = fmaf(e, Lv.x, acc.x);
        acc.y = fmaf(e, Lv.y, acc.y);
    }
    const float inv = 1.0f / s;   // s identical across lanes (same serial loop)
    if (c0 < RR)     out[bag * RR + c0]     = acc.x * inv + bias[c0];
    if (c0 + 1 < RR) out[bag * RR + c0 + 1] = acc.y * inv + bias[c0 + 1];
}

extern "C" void kernel_launch(void* const* d_in, const int* in_sizes, int n_in,
                              void* d_out, int out_size) {
    const float* repre  = (const float*)d_in[0];
    const float* rel    = (const float*)d_in[1];
    const float* bias   = (const float*)d_in[2];
    const int*   scope  = (const int*)d_in[3];
    const int*   labels = (const int*)d_in[4];
    float* out = (float*)d_out;

    const int Mrows    = in_sizes[0] / Dd;    // 200000
    const int num_bags = in_sizes[3] / 2;     // 25000

    convert_kernel<<<1, 256>>>(rel);
    gemm_kernel<<<(Mrows + 127) / 128, 256>>>(repre, Mrows);
    out_kernel<<<(num_bags + 7) / 8, 256>>>(bias, scope, labels, out, num_bags);
}